// round 16
// baseline (speedup 1.0000x reference)
#include <cuda_runtime.h>
#include <cuda_bf16.h>
#include <mma.h>
#include <math.h>

using namespace nvcuda;

#define NN 32768
#define GG 512
#define MAXNODE 64
#define EE 262144
#define NROW 563            // 51 type rows + 512 start rows
#define NROWP 576           // padded to 64 multiple for GEMM tiles

// ---------------- scratch (static device globals; no allocation) ----------------
__device__ float g_start[GG * 128];
__device__ float g_embproj[51 * 128];
__device__ float g_x0t[NROWP * 128];      // layernormed distinct rows (table)
__device__ float g_xp1t[NROWP * 512];     // x0_table @ W1
__device__ __align__(16) __nv_bfloat16 g_x1h[NN * 512];   // conv1 out, bf16 hi
__device__ __align__(16) __nv_bfloat16 g_x1l[NN * 512];   // conv1 out, bf16 lo
__device__ __align__(16) __nv_bfloat16 g_w2h[512 * 128];  // W2 bf16 hi
__device__ __align__(16) __nv_bfloat16 g_w2l[512 * 128];  // W2 bf16 lo
__device__ float g_wa_s[4 * 128];         // W1_blk @ a_src per head
__device__ float g_wa_d[4 * 128];         // W1_blk @ a_dst per head
__device__ float g_als1[NROWP * 4];
__device__ float g_ald1[NROWP * 4];
__device__ float g_xp2[NN * 128];         // x1 @ W2
__device__ float g_als2[NN];
__device__ float g_ald2[NN];
__device__ int   g_rid[NN];               // node -> distinct row id
__device__ int   g_cnt[NN];
__device__ int   g_rowptr[NN + 1];
__device__ int   g_cursor[NN];
__device__ int   g_sorted[EE];            // src sorted by dst
__device__ int   g_sridr[EE];             // rid[src] sorted by dst

// ---------------- helpers ----------------
__device__ __forceinline__ float warp_sum(float v) {
#pragma unroll
    for (int o = 16; o > 0; o >>= 1) v += __shfl_xor_sync(0xffffffffu, v, o);
    return v;
}
__device__ __forceinline__ float lrelu02(float x) { return x > 0.f ? x : 0.2f * x; }
__device__ __forceinline__ float elu1(float x) { return x > 0.f ? x : (__expf(x) - 1.f); }

// =========== K1: prep — tv+start fused, embproj, rid, cnt zero, W2 split, wa fold ===========
// blocks 0..127   : tv+start for 4 graphs each (g_tv stays in smem)
// blocks 128..178 : embproj rows 0..50
// blocks 179..306 : rid + cnt zero (256 nodes each)
// blocks 307..338 : W2 hi/lo split (2048 elems each)
// blocks 339..342 : wa_src/wa_dst fold per head
__global__ __launch_bounds__(256) void k_prep(
    const float* __restrict__ t, const float* __restrict__ v,
    const float* __restrict__ Wt, const float* __restrict__ bt,
    const float* __restrict__ Wv, const float* __restrict__ bv,
    const float* __restrict__ Ws, const float* __restrict__ bs,
    const float* __restrict__ emb, const float* __restrict__ Wn,
    const float* __restrict__ bn, const int* __restrict__ m_idx,
    const float* __restrict__ W2, const float* __restrict__ W1,
    const float* __restrict__ as1, const float* __restrict__ ad1) {
    __shared__ __align__(16) float sm[4 * 768 * 2 + 4 * 256];   // 28KB
    int b = blockIdx.x;
    int tid = threadIdx.x;
    if (b < 128) {
        float (*sv)[768] = (float(*)[768])sm;
        float (*st)[768] = (float(*)[768])(sm + 4 * 768);
        float (*stv)[256] = (float(*)[256])(sm + 8 * 768);
        int g0 = b * 4;
        for (int i = tid; i < 4 * 768; i += 256) {
            int gi = i / 768, k = i - gi * 768;
            sv[gi][k] = v[(g0 + gi) * 768 + k];
            st[gi][k] = t[(g0 + gi) * 768 + k];
        }
        __syncthreads();
        int col = tid & 127;
        bool isv = (tid < 128);
        const float* W = isv ? Wv : Wt;
        float (*S)[768] = isv ? sv : st;
        float acc[4] = {0.f, 0.f, 0.f, 0.f};
        for (int k = 0; k < 768; k++) {
            float w = W[k * 128 + col];
#pragma unroll
            for (int gi = 0; gi < 4; gi++) acc[gi] += S[gi][k] * w;
        }
        float bb = isv ? bv[col] : bt[col];
#pragma unroll
        for (int gi = 0; gi < 4; gi++) stv[gi][tid] = acc[gi] + bb;
        __syncthreads();
        if (tid < 128) {
            float a2[4] = {0.f, 0.f, 0.f, 0.f};
            for (int k = 0; k < 256; k++) {
                float w = Ws[k * 128 + tid];
#pragma unroll
                for (int gi = 0; gi < 4; gi++) a2[gi] += stv[gi][k] * w;
            }
            float b2 = bs[tid];
#pragma unroll
            for (int gi = 0; gi < 4; gi++) g_start[(g0 + gi) * 128 + tid] = a2[gi] + b2;
        }
    } else if (b < 179) {
        int r = b - 128;
        float* se = sm;
        if (tid < 128) se[tid] = emb[r * 128 + tid];
        __syncthreads();
        if (tid < 128) {
            float acc = 0.f;
            for (int k = 0; k < 128; k++) acc += se[k] * Wn[k * 128 + tid];
            g_embproj[r * 128 + tid] = acc + bn[tid];
        }
    } else if (b < 307) {
        int n = (b - 179) * 256 + tid;
        g_cnt[n] = 0;
        int local = n & 63, gg = n >> 6;
        g_rid[n] = (local == 0) ? (51 + gg) : m_idx[n];
    } else if (b < 339) {
        int i0 = ((b - 307) * 256 + tid) * 8;
#pragma unroll
        for (int i = i0; i < i0 + 8; i++) {
            float x = W2[i];
            __nv_bfloat16 hi = __float2bfloat16(x);
            g_w2h[i] = hi;
            g_w2l[i] = __float2bfloat16(x - __bfloat162float(hi));
        }
    } else {
        int h = b - 339;
        if (tid < 128) {
            float ws = 0.f, wd = 0.f;
            const float* wrow = W1 + tid * 512 + h * 128;
            const float* av = as1 + h * 128;
            const float* dv = ad1 + h * 128;
            for (int j = 0; j < 128; j++) {
                float w = wrow[j];
                ws += w * av[j];
                wd += w * dv[j];
            }
            g_wa_s[h * 128 + tid] = ws;
            g_wa_d[h * 128 + tid] = wd;
        }
    }
}

// =========== K2: buildtab + folded attn coefficients (blocks 0..71) + hist (72..1095) ===========
__global__ __launch_bounds__(256) void k_build_hist(
    const float* __restrict__ lg, const float* __restrict__ lb,
    const int* __restrict__ dst) {
    int b = blockIdx.x;
    int tid = threadIdx.x;
    if (b < 72) {
        int r = (b * 256 + tid) >> 5;
        int lane = tid & 31;
        if (r >= NROWP) return;
        if (r >= NROW) {
            *(float4*)(g_x0t + r * 128 + lane * 4) = make_float4(0.f, 0.f, 0.f, 0.f);
            return;
        }
        const float* src = (r < 51) ? (g_embproj + r * 128) : (g_start + (r - 51) * 128);
        float4 x = *(const float4*)(src + lane * 4);
        float mu = warp_sum(x.x + x.y + x.z + x.w) * (1.f / 128.f);
        float dx = x.x - mu, dy = x.y - mu, dz = x.z - mu, dw = x.w - mu;
        float var = warp_sum(dx * dx + dy * dy + dz * dz + dw * dw) * (1.f / 128.f);
        float inv = rsqrtf(var + 1e-6f);
        float4 gv = *(const float4*)(lg + lane * 4);
        float4 bv = *(const float4*)(lb + lane * 4);
        float4 o;
        o.x = dx * inv * gv.x + bv.x;
        o.y = dy * inv * gv.y + bv.y;
        o.z = dz * inv * gv.z + bv.z;
        o.w = dw * inv * gv.w + bv.w;
        *(float4*)(g_x0t + r * 128 + lane * 4) = o;
        // folded attention coefficients: als1[r,h] = o . wa_s[h], ald1 likewise
#pragma unroll
        for (int h = 0; h < 4; h++) {
            float4 was = *(const float4*)(g_wa_s + h * 128 + lane * 4);
            float4 wad = *(const float4*)(g_wa_d + h * 128 + lane * 4);
            float ps = warp_sum(o.x * was.x + o.y * was.y + o.z * was.z + o.w * was.w);
            float pd = warp_sum(o.x * wad.x + o.y * wad.y + o.z * wad.z + o.w * wad.w);
            if (lane == 0) { g_als1[r * 4 + h] = ps; g_ald1[r * 4 + h] = pd; }
        }
    } else {
        int e = (b - 72) * 256 + tid;
        if (e < EE) atomicAdd(&g_cnt[dst[e]], 1);
    }
}

// =========== K3: exclusive scan of counts (1 block) ===========
__global__ void k_scan() {
    __shared__ int ss[1024];
    int t = threadIdx.x;
    int base = t * 32;
    int c[32];
    int s = 0;
#pragma unroll
    for (int i = 0; i < 32; i++) { c[i] = g_cnt[base + i]; s += c[i]; }
    ss[t] = s;
    __syncthreads();
    for (int off = 1; off < 1024; off <<= 1) {
        int v = (t >= off) ? ss[t - off] : 0;
        __syncthreads();
        ss[t] += v;
        __syncthreads();
    }
    int run = ss[t] - s;
#pragma unroll
    for (int i = 0; i < 32; i++) {
        g_rowptr[base + i] = run;
        g_cursor[base + i] = run;
        run += c[i];
    }
    if (t == 1023) g_rowptr[NN] = run;
}

// =========== K4: conv1 table GEMM (blocks 0..71) + CSR scatter (72..1095) ===========
__global__ __launch_bounds__(256) void k_scatter_gemm(
    const int* __restrict__ src, const int* __restrict__ dst,
    const float* __restrict__ B) {
    int b = blockIdx.x;
    int tid = threadIdx.x;
    if (b < 72) {
        __shared__ float As[16][64];
        __shared__ float Bs[16][64];
        const int N = 512, K = 128;
        int bm = (b >> 3) * 64, bn = (b & 7) * 64;
        int tx = tid & 15, ty = tid >> 4;
        float acc[4][4] = {};
        for (int k0 = 0; k0 < K; k0 += 16) {
            int r = tid >> 2, c4 = (tid & 3) << 2;
            float4 av = *(const float4*)&g_x0t[(bm + r) * K + k0 + c4];
            As[c4 + 0][r] = av.x; As[c4 + 1][r] = av.y;
            As[c4 + 2][r] = av.z; As[c4 + 3][r] = av.w;
            int br = tid >> 4, bc = (tid & 15) << 2;
            *(float4*)&Bs[br][bc] = *(const float4*)&B[(k0 + br) * N + bn + bc];
            __syncthreads();
#pragma unroll
            for (int kk = 0; kk < 16; kk++) {
                float4 a = *(const float4*)&As[kk][ty << 2];
                float4 bb = *(const float4*)&Bs[kk][tx << 2];
                acc[0][0] += a.x * bb.x; acc[0][1] += a.x * bb.y; acc[0][2] += a.x * bb.z; acc[0][3] += a.x * bb.w;
                acc[1][0] += a.y * bb.x; acc[1][1] += a.y * bb.y; acc[1][2] += a.y * bb.z; acc[1][3] += a.y * bb.w;
                acc[2][0] += a.z * bb.x; acc[2][1] += a.z * bb.y; acc[2][2] += a.z * bb.z; acc[2][3] += a.z * bb.w;
                acc[3][0] += a.w * bb.x; acc[3][1] += a.w * bb.y; acc[3][2] += a.w * bb.z; acc[3][3] += a.w * bb.w;
            }
            __syncthreads();
        }
#pragma unroll
        for (int i = 0; i < 4; i++) {
            float4 o = make_float4(acc[i][0], acc[i][1], acc[i][2], acc[i][3]);
            *(float4*)&g_xp1t[(bm + (ty << 2) + i) * N + bn + (tx << 2)] = o;
        }
    } else {
        int e = (b - 72) * 256 + tid;
        if (e < EE) {
            int s = src[e];
            int p = atomicAdd(&g_cursor[dst[e]], 1);
            g_sorted[p] = s;
            g_sridr[p] = g_rid[s];
        }
    }
}

// =========== K5: conv1 agg — smem type-row table, single pass, writes bf16 hi/lo ===========
// grid = 4 heads * 128 chunks; block 256 = 8 warps * 32 nodes (256 nodes/block).
__global__ __launch_bounds__(256) void k_agg4bf(const float* __restrict__ xp,
                                                const float* __restrict__ bias) {
    __shared__ float s_tab[51 * 128];    // type rows, this head's 512B segment
    __shared__ float s_as[NROW], s_ad[NROW];
    int h = blockIdx.x >> 7;
    int chunk = blockIdx.x & 127;
    int tid = threadIdx.x;
    for (int i = tid * 4; i < 51 * 128; i += 1024) {
        int r = i >> 7, c = i & 127;
        *(float4*)&s_tab[i] = *(const float4*)&xp[((r * 4 + h) << 7) + c];
    }
    for (int i = tid; i < NROW; i += 256) {
        s_as[i] = g_als1[i * 4 + h];
        s_ad[i] = g_ald1[i * 4 + h];
    }
    __syncthreads();
    int wid = tid >> 5, lane = tid & 31;
    float4 bv = *(const float4*)(bias + h * 128 + lane * 4);
    for (int i = 0; i < 32; i++) {
        int d = (chunk << 8) + (wid << 5) + i;
        int dr = g_rid[d];
        int r0 = g_rowptr[d], r1 = g_rowptr[d + 1];
        float aldd = s_ad[dr];
        float self_s = lrelu02(s_as[dr] + aldd);
        float4 acc;
        if (dr < 51) acc = *(const float4*)&s_tab[(dr << 7) + (lane << 2)];
        else acc = *(const float4*)&xp[((dr * 4 + h) << 7) + (lane << 2)];
        float denom_l = 0.f;
        for (int c0 = r0; c0 < r1; c0 += 32) {
            int e = c0 + lane;
            int sr = 0;
            float w = 0.f;
            if (e < r1) {
                sr = g_sridr[e];
                w = __expf(lrelu02(s_as[sr] + aldd) - self_s);
                denom_l += w;
            }
            int cnt = min(32, r1 - c0);
            for (int k = 0; k < cnt; k++) {
                float wk = __shfl_sync(0xffffffffu, w, k);
                int srk = __shfl_sync(0xffffffffu, sr, k);
                float4 v;
                if (srk < 51) v = *(const float4*)&s_tab[(srk << 7) + (lane << 2)];
                else v = *(const float4*)&xp[((srk * 4 + h) << 7) + (lane << 2)];
                acc.x += wk * v.x; acc.y += wk * v.y; acc.z += wk * v.z; acc.w += wk * v.w;
            }
        }
        float denom = 1.f + warp_sum(denom_l);
        float inv = 1.f / denom;
        float o[4];
        o[0] = elu1(acc.x * inv + bv.x);
        o[1] = elu1(acc.y * inv + bv.y);
        o[2] = elu1(acc.z * inv + bv.z);
        o[3] = elu1(acc.w * inv + bv.w);
        int idx = ((d << 2) + h) * 128 + (lane << 2);
        __nv_bfloat16 hi[4], lo[4];
#pragma unroll
        for (int q = 0; q < 4; q++) {
            hi[q] = __float2bfloat16(o[q]);
            lo[q] = __float2bfloat16(o[q] - __bfloat162float(hi[q]));
        }
        *(__nv_bfloat162*)&g_x1h[idx]     = __nv_bfloat162(hi[0], hi[1]);
        *(__nv_bfloat162*)&g_x1h[idx + 2] = __nv_bfloat162(hi[2], hi[3]);
        *(__nv_bfloat162*)&g_x1l[idx]     = __nv_bfloat162(lo[0], lo[1]);
        *(__nv_bfloat162*)&g_x1l[idx + 2] = __nv_bfloat162(lo[2], lo[3]);
    }
}

// =========== K6: conv2 GEMM (split-bf16 tensor cores, 128-row tile) + attn2 epilogue ===========
__global__ __launch_bounds__(256) void k_wmma_attn(const float* __restrict__ as2,
                                                   const float* __restrict__ ad2) {
    const int K = 512, N = 128;
    // union: [A hi/lo 128x40 + B hi/lo 32x136] (37.9KB) then C half-tile 64x128 f32 (32KB)
    __shared__ __align__(16) char smraw[2 * 128 * 40 * 2 + 2 * 32 * 136 * 2];
    __nv_bfloat16* sAh = (__nv_bfloat16*)smraw;          // [128][40]
    __nv_bfloat16* sAl = sAh + 128 * 40;
    __nv_bfloat16* sBh = sAl + 128 * 40;                 // [32][136]
    __nv_bfloat16* sBl = sBh + 32 * 136;
    float* sC = (float*)smraw;                            // [64][128] after K loop
    int bm = blockIdx.x * 128;
    int tid = threadIdx.x;
    int wid = tid >> 5, lane = tid & 31;
    int wm = (wid & 3) * 32;      // rows 0/32/64/96
    int wn = (wid >> 2) * 64;     // cols 0/64

    wmma::fragment<wmma::accumulator, 16, 16, 16, float> acc[2][4];
#pragma unroll
    for (int i = 0; i < 2; i++)
#pragma unroll
        for (int j = 0; j < 4; j++) wmma::fill_fragment(acc[i][j], 0.f);

    int r = tid >> 1, c = (tid & 1) * 16;   // A: 128 rows x 32 cols, 16 bf16/thread
    int br = tid >> 4, bc = (tid & 15) * 8; // B: rows br, br+16

    for (int k0 = 0; k0 < K; k0 += 32) {
        *(uint4*)&sAh[r * 40 + c]     = *(const uint4*)&g_x1h[(bm + r) * K + k0 + c];
        *(uint4*)&sAh[r * 40 + c + 8] = *(const uint4*)&g_x1h[(bm + r) * K + k0 + c + 8];
        *(uint4*)&sAl[r * 40 + c]     = *(const uint4*)&g_x1l[(bm + r) * K + k0 + c];
        *(uint4*)&sAl[r * 40 + c + 8] = *(const uint4*)&g_x1l[(bm + r) * K + k0 + c + 8];
        *(uint4*)&sBh[br * 136 + bc]        = *(const uint4*)&g_w2h[(k0 + br) * N + bc];
        *(uint4*)&sBh[(br + 16) * 136 + bc] = *(const uint4*)&g_w2h[(k0 + br + 16) * N + bc];
        *(uint4*)&sBl[br * 136 + bc]        = *(const uint4*)&g_w2l[(k0 + br) * N + bc];
        *(uint4*)&sBl[(br + 16) * 136 + bc] = *(const uint4*)&g_w2l[(k0 + br + 16) * N + bc];
        __syncthreads();
#pragma unroll
        for (int ks = 0; ks < 2; ks++) {
            wmma::fragment<wmma::matrix_a, 16, 16, 16, __nv_bfloat16, wmma::row_major> fAh[2], fAl[2];
            wmma::fragment<wmma::matrix_b, 16, 16, 16, __nv_bfloat16, wmma::row_major> fBh[4], fBl[4];
#pragma unroll
            for (int i = 0; i < 2; i++) {
                wmma::load_matrix_sync(fAh[i], &sAh[(wm + i * 16) * 40 + ks * 16], 40);
                wmma::load_matrix_sync(fAl[i], &sAl[(wm + i * 16) * 40 + ks * 16], 40);
            }
#pragma unroll
            for (int j = 0; j < 4; j++) {
                wmma::load_matrix_sync(fBh[j], &sBh[(ks * 16) * 136 + wn + j * 16], 136);
                wmma::load_matrix_sync(fBl[j], &sBl[(ks * 16) * 136 + wn + j * 16], 136);
            }
#pragma unroll
            for (int i = 0; i < 2; i++)
#pragma unroll
                for (int j = 0; j < 4; j++) {
                    wmma::mma_sync(acc[i][j], fAh[i], fBh[j], acc[i][j]);
                    wmma::mma_sync(acc[i][j], fAh[i], fBl[j], acc[i][j]);
                    wmma::mma_sync(acc[i][j], fAl[i], fBh[j], acc[i][j]);
                }
        }
        __syncthreads();
    }
    // two-phase epilogue: 64 rows at a time through the reused smem C tile
    float4 a4 = *(const float4*)(as2 + lane * 4);
    float4 d4 = *(const float4*)(ad2 + lane * 4);
#pragma unroll
    for (int ph = 0; ph < 2; ph++) {
        if ((wm >> 6) == ph) {   // warps owning rows [ph*64, ph*64+64)
#pragma unroll
            for (int i = 0; i < 2; i++)
#pragma unroll
                for (int j = 0; j < 4; j++)
                    wmma::store_matrix_sync(&sC[(wm - ph * 64 + i * 16) * 128 + wn + j * 16],
                                            acc[i][j], 128, wmma::mem_row_major);
        }
        __syncthreads();
#pragma unroll
        for (int rr = 0; rr < 8; rr++) {
            int row = wid * 8 + rr;               // 0..63
            int grow = bm + ph * 64 + row;
            float4 x = *(float4*)&sC[row * 128 + lane * 4];
            *(float4*)&g_xp2[grow * 128 + lane * 4] = x;
            float ps = warp_sum(x.x * a4.x + x.y * a4.y + x.z * a4.z + x.w * a4.w);
            float pd = warp_sum(x.x * d4.x + x.y * d4.y + x.z * d4.z + x.w * d4.w);
            if (lane == 0) { g_als2[grow] = ps; g_ald2[grow] = pd; }
        }
        __syncthreads();
    }
}

// =========== K7: conv2 agg + masked mean pool + output head (block per graph) ===========
__global__ __launch_bounds__(512) void k_final(
    const float* __restrict__ b2, const int* __restrict__ m_idx,
    const float* __restrict__ Wo1, const float* __restrict__ bo1,
    const float* __restrict__ Wo2, const float* __restrict__ bo2,
    float* __restrict__ out) {
    __shared__ float sx2[64][128];    // 32KB
    __shared__ float sp[128];
    __shared__ float red[128];
    int g = blockIdx.x;
    int tid = threadIdx.x;
    int wid = tid >> 5, lane = tid & 31;
    float4 bv = *(const float4*)(b2 + lane * 4);
    for (int i = 0; i < 4; i++) {
        int ln = (wid << 2) + i;     // local node 0..63
        int d = (g << 6) + ln;
        int r0 = g_rowptr[d], r1 = g_rowptr[d + 1];
        float aldd = g_ald2[d];
        float self_s = lrelu02(g_als2[d] + aldd);
        float4 acc = *(const float4*)&g_xp2[d * 128 + (lane << 2)];
        float denom_l = 0.f;
        for (int c0 = r0; c0 < r1; c0 += 32) {
            int e = c0 + lane;
            int s = 0;
            float w = 0.f;
            if (e < r1) {
                s = g_sorted[e];
                w = __expf(lrelu02(g_als2[s] + aldd) - self_s);
                denom_l += w;
            }
            int cnt = min(32, r1 - c0);
            for (int k = 0; k < cnt; k++) {
                float wk = __shfl_sync(0xffffffffu, w, k);
                int sk = __shfl_sync(0xffffffffu, s, k);
                float4 vv = *(const float4*)&g_xp2[sk * 128 + (lane << 2)];
                acc.x += wk * vv.x; acc.y += wk * vv.y; acc.z += wk * vv.z; acc.w += wk * vv.w;
            }
        }
        float denom = 1.f + warp_sum(denom_l);
        float inv = 1.f / denom;
        sx2[ln][(lane << 2) + 0] = elu1(acc.x * inv + bv.x);
        sx2[ln][(lane << 2) + 1] = elu1(acc.y * inv + bv.y);
        sx2[ln][(lane << 2) + 2] = elu1(acc.z * inv + bv.z);
        sx2[ln][(lane << 2) + 3] = elu1(acc.w * inv + bv.w);
    }
    __syncthreads();
    if (tid < 128) {
        float s = 0.f;
        int cnt = 0;
        for (int n = 0; n < 64; n++) {
            if (m_idx[(g << 6) + n] >= 1) { s += sx2[n][tid]; cnt++; }
        }
        sp[tid] = s / (float)cnt;
    }
    __syncthreads();
    if (tid < 128) {
        float acc = 0.f;
        for (int k = 0; k < 128; k++) acc += sp[k] * Wo1[k * 128 + tid];
        acc += bo1[tid];
        float h1 = acc > 0.f ? acc : 0.01f * acc;
        red[tid] = h1 * Wo2[tid];
    }
    __syncthreads();
    for (int off = 64; off > 0; off >>= 1) {
        if (tid < off) red[tid] += red[tid + off];
        __syncthreads();
    }
    if (tid == 0) out[g] = red[0] + bo2[0];
}

// ---------------- host ----------------
extern "C" void kernel_launch(void* const* d_in, const int* in_sizes, int n_in,
                              void* d_out, int out_size) {
    int it, iv, im, iei, iWt, ibt, iWv, ibv, iemb, iWn, ibn, iWs, ibs, ilg, ilb;
    int iW1, ias1, iad1, ib1, iW2, ias2, iad2, ib2, iWo1, ibo1, iWo2, ibo2;
    if (in_sizes[2] == NN) {   // setup_inputs dict order
        it = 0; iv = 1; im = 2; iei = 3; iWt = 4; ibt = 5; iWv = 6; ibv = 7;
        iemb = 8; iWn = 9; ibn = 10; iWs = 11; ibs = 12; ilg = 13; ilb = 14;
        iW1 = 15; ias1 = 16; iad1 = 17; ib1 = 18; iW2 = 19; ias2 = 20; iad2 = 21;
        ib2 = 22; iWo1 = 23; ibo1 = 24; iWo2 = 25; ibo2 = 26;
    } else {                   // reference() signature order
        it = 0; iv = 1; iWt = 2; ibt = 3; iWv = 4; ibv = 5; iemb = 6; iWn = 7;
        ibn = 8; iWs = 9; ibs = 10; ilg = 11; ilb = 12; iW1 = 13; ias1 = 14;
        iad1 = 15; ib1 = 16; iW2 = 17; ias2 = 18; iad2 = 19; ib2 = 20;
        iWo1 = 21; ibo1 = 22; iWo2 = 23; ibo2 = 24; im = 25; iei = 26;
    }
    const float* t   = (const float*)d_in[it];
    const float* v   = (const float*)d_in[iv];
    const int*   mi  = (const int*)d_in[im];
    const int*   ei  = (const int*)d_in[iei];
    const float* Wt  = (const float*)d_in[iWt];
    const float* bt  = (const float*)d_in[ibt];
    const float* Wv  = (const float*)d_in[iWv];
    const float* bv  = (const float*)d_in[ibv];
    const float* emb = (const float*)d_in[iemb];
    const float* Wn  = (const float*)d_in[iWn];
    const float* bn  = (const float*)d_in[ibn];
    const float* Ws  = (const float*)d_in[iWs];
    const float* bs  = (const float*)d_in[ibs];
    const float* lg  = (const float*)d_in[ilg];
    const float* lb  = (const float*)d_in[ilb];
    const float* W1  = (const float*)d_in[iW1];
    const float* as1 = (const float*)d_in[ias1];
    const float* ad1 = (const float*)d_in[iad1];
    const float* b1  = (const float*)d_in[ib1];
    const float* W2  = (const float*)d_in[iW2];
    const float* as2 = (const float*)d_in[ias2];
    const float* ad2 = (const float*)d_in[iad2];
    const float* b2  = (const float*)d_in[ib2];
    const float* Wo1 = (const float*)d_in[iWo1];
    const float* bo1 = (const float*)d_in[ibo1];
    const float* Wo2 = (const float*)d_in[iWo2];
    const float* bo2 = (const float*)d_in[ibo2];
    const int* esrc = ei;
    const int* edst = ei + EE;

    float *p_xp1t;
    cudaGetSymbolAddress((void**)&p_xp1t, g_xp1t);

    k_prep<<<343, 256>>>(t, v, Wt, bt, Wv, bv, Ws, bs, emb, Wn, bn, mi, W2, W1, as1, ad1);
    k_build_hist<<<1096, 256>>>(lg, lb, edst);
    k_scan<<<1, 1024>>>();
    k_scatter_gemm<<<1096, 256>>>(esrc, edst, W1);
    k_agg4bf<<<512, 256>>>(p_xp1t, b1);
    k_wmma_attn<<<NN / 128, 256>>>(as2, ad2);
    k_final<<<GG, 512>>>(b2, mi, Wo1, bo1, Wo2, bo2, (float*)d_out);
}

// round 17
// speedup vs baseline: 1.0500x; 1.0500x over previous
#include <cuda_runtime.h>
#include <cuda_bf16.h>
#include <mma.h>
#include <math.h>

using namespace nvcuda;

#define NN 32768
#define GG 512
#define MAXNODE 64
#define EE 262144
#define NROW 563            // 51 type rows + 512 start rows
#define NROWP 576           // padded to 64 multiple for GEMM tiles

// ---------------- scratch (static device globals; no allocation) ----------------
__device__ float g_start[GG * 128];
__device__ float g_embproj[51 * 128];
__device__ float g_x0t[NROWP * 128];      // layernormed distinct rows (table)
__device__ float g_xp1t[NROWP * 512];     // x0_table @ W1
__device__ __align__(16) __nv_bfloat16 g_x1h[NN * 512];   // conv1 out, bf16 hi
__device__ __align__(16) __nv_bfloat16 g_x1l[NN * 512];   // conv1 out, bf16 lo
__device__ __align__(16) __nv_bfloat16 g_w2h[512 * 128];  // W2 bf16 hi
__device__ __align__(16) __nv_bfloat16 g_w2l[512 * 128];  // W2 bf16 lo
__device__ float g_wa_s[4 * 128];         // W1_blk @ a_src per head
__device__ float g_wa_d[4 * 128];         // W1_blk @ a_dst per head
__device__ float g_als1[NROWP * 4];
__device__ float g_ald1[NROWP * 4];
__device__ float g_xp2[NN * 128];         // x1 @ W2
__device__ float g_als2[NN];
__device__ float g_ald2[NN];
__device__ int   g_rid[NN];               // node -> distinct row id
__device__ int   g_cnt[NN];
__device__ int   g_rowptr[NN + 1];
__device__ int   g_cursor[NN];
__device__ int   g_sorted[EE];            // src sorted by dst
__device__ int   g_sridr[EE];             // rid[src] sorted by dst

// ---------------- helpers ----------------
__device__ __forceinline__ float warp_sum(float v) {
#pragma unroll
    for (int o = 16; o > 0; o >>= 1) v += __shfl_xor_sync(0xffffffffu, v, o);
    return v;
}
__device__ __forceinline__ float lrelu02(float x) { return x > 0.f ? x : 0.2f * x; }
__device__ __forceinline__ float elu1(float x) { return x > 0.f ? x : (__expf(x) - 1.f); }

// =========== K1: prep — tv+start fused, embproj, rid, cnt zero, W2 split, wa fold ===========
// blocks 0..127   : tv+start for 4 graphs each (g_tv stays in smem)
// blocks 128..178 : embproj rows 0..50
// blocks 179..306 : rid + cnt zero (256 nodes each)
// blocks 307..338 : W2 hi/lo split (2048 elems each)
// blocks 339..342 : wa_src/wa_dst fold per head
__global__ __launch_bounds__(256) void k_prep(
    const float* __restrict__ t, const float* __restrict__ v,
    const float* __restrict__ Wt, const float* __restrict__ bt,
    const float* __restrict__ Wv, const float* __restrict__ bv,
    const float* __restrict__ Ws, const float* __restrict__ bs,
    const float* __restrict__ emb, const float* __restrict__ Wn,
    const float* __restrict__ bn, const int* __restrict__ m_idx,
    const float* __restrict__ W2, const float* __restrict__ W1,
    const float* __restrict__ as1, const float* __restrict__ ad1) {
    __shared__ __align__(16) float sm[4 * 768 * 2 + 4 * 256];   // 28KB
    int b = blockIdx.x;
    int tid = threadIdx.x;
    if (b < 128) {
        float (*sv)[768] = (float(*)[768])sm;
        float (*st)[768] = (float(*)[768])(sm + 4 * 768);
        float (*stv)[256] = (float(*)[256])(sm + 8 * 768);
        int g0 = b * 4;
        for (int i = tid; i < 4 * 768; i += 256) {
            int gi = i / 768, k = i - gi * 768;
            sv[gi][k] = v[(g0 + gi) * 768 + k];
            st[gi][k] = t[(g0 + gi) * 768 + k];
        }
        __syncthreads();
        int col = tid & 127;
        bool isv = (tid < 128);
        const float* W = isv ? Wv : Wt;
        float (*S)[768] = isv ? sv : st;
        float acc[4] = {0.f, 0.f, 0.f, 0.f};
        for (int k = 0; k < 768; k++) {
            float w = W[k * 128 + col];
#pragma unroll
            for (int gi = 0; gi < 4; gi++) acc[gi] += S[gi][k] * w;
        }
        float bb = isv ? bv[col] : bt[col];
#pragma unroll
        for (int gi = 0; gi < 4; gi++) stv[gi][tid] = acc[gi] + bb;
        __syncthreads();
        if (tid < 128) {
            float a2[4] = {0.f, 0.f, 0.f, 0.f};
            for (int k = 0; k < 256; k++) {
                float w = Ws[k * 128 + tid];
#pragma unroll
                for (int gi = 0; gi < 4; gi++) a2[gi] += stv[gi][k] * w;
            }
            float b2 = bs[tid];
#pragma unroll
            for (int gi = 0; gi < 4; gi++) g_start[(g0 + gi) * 128 + tid] = a2[gi] + b2;
        }
    } else if (b < 179) {
        int r = b - 128;
        float* se = sm;
        if (tid < 128) se[tid] = emb[r * 128 + tid];
        __syncthreads();
        if (tid < 128) {
            float acc = 0.f;
            for (int k = 0; k < 128; k++) acc += se[k] * Wn[k * 128 + tid];
            g_embproj[r * 128 + tid] = acc + bn[tid];
        }
    } else if (b < 307) {
        int n = (b - 179) * 256 + tid;
        g_cnt[n] = 0;
        int local = n & 63, gg = n >> 6;
        g_rid[n] = (local == 0) ? (51 + gg) : m_idx[n];
    } else if (b < 339) {
        int i0 = ((b - 307) * 256 + tid) * 8;
#pragma unroll
        for (int i = i0; i < i0 + 8; i++) {
            float x = W2[i];
            __nv_bfloat16 hi = __float2bfloat16(x);
            g_w2h[i] = hi;
            g_w2l[i] = __float2bfloat16(x - __bfloat162float(hi));
        }
    } else {
        int h = b - 339;
        if (tid < 128) {
            float ws = 0.f, wd = 0.f;
            const float* wrow = W1 + tid * 512 + h * 128;
            const float* av = as1 + h * 128;
            const float* dv = ad1 + h * 128;
            for (int j = 0; j < 128; j++) {
                float w = wrow[j];
                ws += w * av[j];
                wd += w * dv[j];
            }
            g_wa_s[h * 128 + tid] = ws;
            g_wa_d[h * 128 + tid] = wd;
        }
    }
}

// =========== K2: buildtab + folded attn coefficients (blocks 0..71) + hist (72..1095) ===========
__global__ __launch_bounds__(256) void k_build_hist(
    const float* __restrict__ lg, const float* __restrict__ lb,
    const int* __restrict__ dst) {
    int b = blockIdx.x;
    int tid = threadIdx.x;
    if (b < 72) {
        int r = (b * 256 + tid) >> 5;
        int lane = tid & 31;
        if (r >= NROWP) return;
        if (r >= NROW) {
            *(float4*)(g_x0t + r * 128 + lane * 4) = make_float4(0.f, 0.f, 0.f, 0.f);
            return;
        }
        const float* src = (r < 51) ? (g_embproj + r * 128) : (g_start + (r - 51) * 128);
        float4 x = *(const float4*)(src + lane * 4);
        float mu = warp_sum(x.x + x.y + x.z + x.w) * (1.f / 128.f);
        float dx = x.x - mu, dy = x.y - mu, dz = x.z - mu, dw = x.w - mu;
        float var = warp_sum(dx * dx + dy * dy + dz * dz + dw * dw) * (1.f / 128.f);
        float inv = rsqrtf(var + 1e-6f);
        float4 gv = *(const float4*)(lg + lane * 4);
        float4 bv = *(const float4*)(lb + lane * 4);
        float4 o;
        o.x = dx * inv * gv.x + bv.x;
        o.y = dy * inv * gv.y + bv.y;
        o.z = dz * inv * gv.z + bv.z;
        o.w = dw * inv * gv.w + bv.w;
        *(float4*)(g_x0t + r * 128 + lane * 4) = o;
        // folded attention coefficients: als1[r,h] = o . wa_s[h], ald1 likewise
#pragma unroll
        for (int h = 0; h < 4; h++) {
            float4 was = *(const float4*)(g_wa_s + h * 128 + lane * 4);
            float4 wad = *(const float4*)(g_wa_d + h * 128 + lane * 4);
            float ps = warp_sum(o.x * was.x + o.y * was.y + o.z * was.z + o.w * was.w);
            float pd = warp_sum(o.x * wad.x + o.y * wad.y + o.z * wad.z + o.w * wad.w);
            if (lane == 0) { g_als1[r * 4 + h] = ps; g_ald1[r * 4 + h] = pd; }
        }
    } else {
        int e = (b - 72) * 256 + tid;
        if (e < EE) atomicAdd(&g_cnt[dst[e]], 1);
    }
}

// =========== K3: exclusive scan of counts (1 block) ===========
__global__ void k_scan() {
    __shared__ int ss[1024];
    int t = threadIdx.x;
    int base = t * 32;
    int c[32];
    int s = 0;
#pragma unroll
    for (int i = 0; i < 32; i++) { c[i] = g_cnt[base + i]; s += c[i]; }
    ss[t] = s;
    __syncthreads();
    for (int off = 1; off < 1024; off <<= 1) {
        int v = (t >= off) ? ss[t - off] : 0;
        __syncthreads();
        ss[t] += v;
        __syncthreads();
    }
    int run = ss[t] - s;
#pragma unroll
    for (int i = 0; i < 32; i++) {
        g_rowptr[base + i] = run;
        g_cursor[base + i] = run;
        run += c[i];
    }
    if (t == 1023) g_rowptr[NN] = run;
}

// =========== K4: conv1 table GEMM (blocks 0..71) + CSR scatter (72..1095) ===========
__global__ __launch_bounds__(256) void k_scatter_gemm(
    const int* __restrict__ src, const int* __restrict__ dst,
    const float* __restrict__ B) {
    int b = blockIdx.x;
    int tid = threadIdx.x;
    if (b < 72) {
        __shared__ float As[16][64];
        __shared__ float Bs[16][64];
        const int N = 512, K = 128;
        int bm = (b >> 3) * 64, bn = (b & 7) * 64;
        int tx = tid & 15, ty = tid >> 4;
        float acc[4][4] = {};
        for (int k0 = 0; k0 < K; k0 += 16) {
            int r = tid >> 2, c4 = (tid & 3) << 2;
            float4 av = *(const float4*)&g_x0t[(bm + r) * K + k0 + c4];
            As[c4 + 0][r] = av.x; As[c4 + 1][r] = av.y;
            As[c4 + 2][r] = av.z; As[c4 + 3][r] = av.w;
            int br = tid >> 4, bc = (tid & 15) << 2;
            *(float4*)&Bs[br][bc] = *(const float4*)&B[(k0 + br) * N + bn + bc];
            __syncthreads();
#pragma unroll
            for (int kk = 0; kk < 16; kk++) {
                float4 a = *(const float4*)&As[kk][ty << 2];
                float4 bb = *(const float4*)&Bs[kk][tx << 2];
                acc[0][0] += a.x * bb.x; acc[0][1] += a.x * bb.y; acc[0][2] += a.x * bb.z; acc[0][3] += a.x * bb.w;
                acc[1][0] += a.y * bb.x; acc[1][1] += a.y * bb.y; acc[1][2] += a.y * bb.z; acc[1][3] += a.y * bb.w;
                acc[2][0] += a.z * bb.x; acc[2][1] += a.z * bb.y; acc[2][2] += a.z * bb.z; acc[2][3] += a.z * bb.w;
                acc[3][0] += a.w * bb.x; acc[3][1] += a.w * bb.y; acc[3][2] += a.w * bb.z; acc[3][3] += a.w * bb.w;
            }
            __syncthreads();
        }
#pragma unroll
        for (int i = 0; i < 4; i++) {
            float4 o = make_float4(acc[i][0], acc[i][1], acc[i][2], acc[i][3]);
            *(float4*)&g_xp1t[(bm + (ty << 2) + i) * N + bn + (tx << 2)] = o;
        }
    } else {
        int e = (b - 72) * 256 + tid;
        if (e < EE) {
            int s = src[e];
            int p = atomicAdd(&g_cursor[dst[e]], 1);
            g_sorted[p] = s;
            g_sridr[p] = g_rid[s];
        }
    }
}

// =========== K5: conv1 agg — smem type-row table, single pass, writes bf16 hi/lo ===========
// grid = 4 heads * 512 chunks; block 256 = 8 warps * 8 nodes (round-15 measured-best shape).
__global__ __launch_bounds__(256) void k_agg4bf(const float* __restrict__ xp,
                                                const float* __restrict__ bias) {
    __shared__ float s_tab[51 * 128];    // type rows, this head's 512B segment
    __shared__ float s_as[NROW], s_ad[NROW];
    int h = blockIdx.x >> 9;
    int chunk = blockIdx.x & 511;
    int tid = threadIdx.x;
    for (int i = tid * 4; i < 51 * 128; i += 1024) {
        int r = i >> 7, c = i & 127;
        *(float4*)&s_tab[i] = *(const float4*)&xp[((r * 4 + h) << 7) + c];
    }
    for (int i = tid; i < NROW; i += 256) {
        s_as[i] = g_als1[i * 4 + h];
        s_ad[i] = g_ald1[i * 4 + h];
    }
    __syncthreads();
    int wid = tid >> 5, lane = tid & 31;
    float4 bv = *(const float4*)(bias + h * 128 + lane * 4);
    for (int i = 0; i < 8; i++) {
        int d = (chunk << 6) + (wid << 3) + i;
        int dr = g_rid[d];
        int r0 = g_rowptr[d], r1 = g_rowptr[d + 1];
        float aldd = s_ad[dr];
        float self_s = lrelu02(s_as[dr] + aldd);
        float4 acc;
        if (dr < 51) acc = *(const float4*)&s_tab[(dr << 7) + (lane << 2)];
        else acc = *(const float4*)&xp[((dr * 4 + h) << 7) + (lane << 2)];
        float denom_l = 0.f;
        for (int c0 = r0; c0 < r1; c0 += 32) {
            int e = c0 + lane;
            int sr = 0;
            float w = 0.f;
            if (e < r1) {
                sr = g_sridr[e];
                w = __expf(lrelu02(s_as[sr] + aldd) - self_s);
                denom_l += w;
            }
            int cnt = min(32, r1 - c0);
            for (int k = 0; k < cnt; k++) {
                float wk = __shfl_sync(0xffffffffu, w, k);
                int srk = __shfl_sync(0xffffffffu, sr, k);
                float4 v;
                if (srk < 51) v = *(const float4*)&s_tab[(srk << 7) + (lane << 2)];
                else v = *(const float4*)&xp[((srk * 4 + h) << 7) + (lane << 2)];
                acc.x += wk * v.x; acc.y += wk * v.y; acc.z += wk * v.z; acc.w += wk * v.w;
            }
        }
        float denom = 1.f + warp_sum(denom_l);
        float inv = 1.f / denom;
        float o[4];
        o[0] = elu1(acc.x * inv + bv.x);
        o[1] = elu1(acc.y * inv + bv.y);
        o[2] = elu1(acc.z * inv + bv.z);
        o[3] = elu1(acc.w * inv + bv.w);
        int idx = ((d << 2) + h) * 128 + (lane << 2);
        __nv_bfloat16 hi[4], lo[4];
#pragma unroll
        for (int q = 0; q < 4; q++) {
            hi[q] = __float2bfloat16(o[q]);
            lo[q] = __float2bfloat16(o[q] - __bfloat162float(hi[q]));
        }
        *(__nv_bfloat162*)&g_x1h[idx]     = __nv_bfloat162(hi[0], hi[1]);
        *(__nv_bfloat162*)&g_x1h[idx + 2] = __nv_bfloat162(hi[2], hi[3]);
        *(__nv_bfloat162*)&g_x1l[idx]     = __nv_bfloat162(lo[0], lo[1]);
        *(__nv_bfloat162*)&g_x1l[idx + 2] = __nv_bfloat162(lo[2], lo[3]);
    }
}

// =========== K6: conv2 GEMM (split-bf16 tensor cores, 64-row tile) + attn2 epilogue ===========
// round-15 measured-best shape: 64-row tile, 32KB smem union, single-phase epilogue.
__global__ __launch_bounds__(256) void k_wmma_attn(const float* __restrict__ as2,
                                                   const float* __restrict__ ad2) {
    const int K = 512, N = 128;
    __shared__ __align__(16) char smraw[64 * 128 * 4];   // 32KB, reused
    __nv_bfloat16* sAh = (__nv_bfloat16*)smraw;          // [64][40]
    __nv_bfloat16* sAl = sAh + 64 * 40;
    __nv_bfloat16* sBh = sAl + 64 * 40;                  // [32][136]
    __nv_bfloat16* sBl = sBh + 32 * 136;
    float* sC = (float*)smraw;                            // [64][128] after K loop
    int bm = blockIdx.x * 64;
    int tid = threadIdx.x;
    int wid = tid >> 5, lane = tid & 31;
    int wm = (wid & 1) * 32;
    int wn = (wid >> 1) * 32;

    wmma::fragment<wmma::accumulator, 16, 16, 16, float> acc[2][2];
#pragma unroll
    for (int i = 0; i < 2; i++)
#pragma unroll
        for (int j = 0; j < 2; j++) wmma::fill_fragment(acc[i][j], 0.f);

    int r = tid >> 2, c = (tid & 3) * 8;
    int br = tid >> 4, bc = (tid & 15) * 8;

    for (int k0 = 0; k0 < K; k0 += 32) {
        *(uint4*)&sAh[r * 40 + c] = *(const uint4*)&g_x1h[(bm + r) * K + k0 + c];
        *(uint4*)&sAl[r * 40 + c] = *(const uint4*)&g_x1l[(bm + r) * K + k0 + c];
        *(uint4*)&sBh[br * 136 + bc]        = *(const uint4*)&g_w2h[(k0 + br) * N + bc];
        *(uint4*)&sBh[(br + 16) * 136 + bc] = *(const uint4*)&g_w2h[(k0 + br + 16) * N + bc];
        *(uint4*)&sBl[br * 136 + bc]        = *(const uint4*)&g_w2l[(k0 + br) * N + bc];
        *(uint4*)&sBl[(br + 16) * 136 + bc] = *(const uint4*)&g_w2l[(k0 + br + 16) * N + bc];
        __syncthreads();
#pragma unroll
        for (int ks = 0; ks < 2; ks++) {
            wmma::fragment<wmma::matrix_a, 16, 16, 16, __nv_bfloat16, wmma::row_major> fAh[2], fAl[2];
            wmma::fragment<wmma::matrix_b, 16, 16, 16, __nv_bfloat16, wmma::row_major> fBh[2], fBl[2];
#pragma unroll
            for (int i = 0; i < 2; i++) {
                wmma::load_matrix_sync(fAh[i], &sAh[(wm + i * 16) * 40 + ks * 16], 40);
                wmma::load_matrix_sync(fAl[i], &sAl[(wm + i * 16) * 40 + ks * 16], 40);
            }
#pragma unroll
            for (int j = 0; j < 2; j++) {
                wmma::load_matrix_sync(fBh[j], &sBh[(ks * 16) * 136 + wn + j * 16], 136);
                wmma::load_matrix_sync(fBl[j], &sBl[(ks * 16) * 136 + wn + j * 16], 136);
            }
#pragma unroll
            for (int i = 0; i < 2; i++)
#pragma unroll
                for (int j = 0; j < 2; j++) {
                    wmma::mma_sync(acc[i][j], fAh[i], fBh[j], acc[i][j]);
                    wmma::mma_sync(acc[i][j], fAh[i], fBl[j], acc[i][j]);
                    wmma::mma_sync(acc[i][j], fAl[i], fBh[j], acc[i][j]);
                }
        }
        __syncthreads();
    }
    // land C tile in smem, then write + attention dots
#pragma unroll
    for (int i = 0; i < 2; i++)
#pragma unroll
        for (int j = 0; j < 2; j++)
            wmma::store_matrix_sync(&sC[(wm + i * 16) * 128 + wn + j * 16], acc[i][j],
                                    128, wmma::mem_row_major);
    __syncthreads();
    float4 a4 = *(const float4*)(as2 + lane * 4);
    float4 d4 = *(const float4*)(ad2 + lane * 4);
#pragma unroll
    for (int rr = 0; rr < 8; rr++) {
        int row = wid * 8 + rr;
        float4 x = *(float4*)&sC[row * 128 + lane * 4];
        *(float4*)&g_xp2[(bm + row) * 128 + lane * 4] = x;
        float ps = warp_sum(x.x * a4.x + x.y * a4.y + x.z * a4.z + x.w * a4.w);
        float pd = warp_sum(x.x * d4.x + x.y * d4.y + x.z * d4.z + x.w * d4.w);
        if (lane == 0) { g_als2[bm + row] = ps; g_ald2[bm + row] = pd; }
    }
}

// =========== K7: conv2 agg + masked mean pool + output head (block per graph) ===========
__global__ __launch_bounds__(512) void k_final(
    const float* __restrict__ b2, const int* __restrict__ m_idx,
    const float* __restrict__ Wo1, const float* __restrict__ bo1,
    const float* __restrict__ Wo2, const float* __restrict__ bo2,
    float* __restrict__ out) {
    __shared__ float sx2[64][128];    // 32KB
    __shared__ float sp[128];
    __shared__ float red[128];
    int g = blockIdx.x;
    int tid = threadIdx.x;
    int wid = tid >> 5, lane = tid & 31;
    float4 bv = *(const float4*)(b2 + lane * 4);
    for (int i = 0; i < 4; i++) {
        int ln = (wid << 2) + i;     // local node 0..63
        int d = (g << 6) + ln;
        int r0 = g_rowptr[d], r1 = g_rowptr[d + 1];
        float aldd = g_ald2[d];
        float self_s = lrelu02(g_als2[d] + aldd);
        float4 acc = *(const float4*)&g_xp2[d * 128 + (lane << 2)];
        float denom_l = 0.f;
        for (int c0 = r0; c0 < r1; c0 += 32) {
            int e = c0 + lane;
            int s = 0;
            float w = 0.f;
            if (e < r1) {
                s = g_sorted[e];
                w = __expf(lrelu02(g_als2[s] + aldd) - self_s);
                denom_l += w;
            }
            int cnt = min(32, r1 - c0);
            for (int k = 0; k < cnt; k++) {
                float wk = __shfl_sync(0xffffffffu, w, k);
                int sk = __shfl_sync(0xffffffffu, s, k);
                float4 vv = *(const float4*)&g_xp2[sk * 128 + (lane << 2)];
                acc.x += wk * vv.x; acc.y += wk * vv.y; acc.z += wk * vv.z; acc.w += wk * vv.w;
            }
        }
        float denom = 1.f + warp_sum(denom_l);
        float inv = 1.f / denom;
        sx2[ln][(lane << 2) + 0] = elu1(acc.x * inv + bv.x);
        sx2[ln][(lane << 2) + 1] = elu1(acc.y * inv + bv.y);
        sx2[ln][(lane << 2) + 2] = elu1(acc.z * inv + bv.z);
        sx2[ln][(lane << 2) + 3] = elu1(acc.w * inv + bv.w);
    }
    __syncthreads();
    if (tid < 128) {
        float s = 0.f;
        int cnt = 0;
        for (int n = 0; n < 64; n++) {
            if (m_idx[(g << 6) + n] >= 1) { s += sx2[n][tid]; cnt++; }
        }
        sp[tid] = s / (float)cnt;
    }
    __syncthreads();
    if (tid < 128) {
        float acc = 0.f;
        for (int k = 0; k < 128; k++) acc += sp[k] * Wo1[k * 128 + tid];
        acc += bo1[tid];
        float h1 = acc > 0.f ? acc : 0.01f * acc;
        red[tid] = h1 * Wo2[tid];
    }
    __syncthreads();
    for (int off = 64; off > 0; off >>= 1) {
        if (tid < off) red[tid] += red[tid + off];
        __syncthreads();
    }
    if (tid == 0) out[g] = red[0] + bo2[0];
}

// ---------------- host ----------------
extern "C" void kernel_launch(void* const* d_in, const int* in_sizes, int n_in,
                              void* d_out, int out_size) {
    int it, iv, im, iei, iWt, ibt, iWv, ibv, iemb, iWn, ibn, iWs, ibs, ilg, ilb;
    int iW1, ias1, iad1, ib1, iW2, ias2, iad2, ib2, iWo1, ibo1, iWo2, ibo2;
    if (in_sizes[2] == NN) {   // setup_inputs dict order
        it = 0; iv = 1; im = 2; iei = 3; iWt = 4; ibt = 5; iWv = 6; ibv = 7;
        iemb = 8; iWn = 9; ibn = 10; iWs = 11; ibs = 12; ilg = 13; ilb = 14;
        iW1 = 15; ias1 = 16; iad1 = 17; ib1 = 18; iW2 = 19; ias2 = 20; iad2 = 21;
        ib2 = 22; iWo1 = 23; ibo1 = 24; iWo2 = 25; ibo2 = 26;
    } else {                   // reference() signature order
        it = 0; iv = 1; iWt = 2; ibt = 3; iWv = 4; ibv = 5; iemb = 6; iWn = 7;
        ibn = 8; iWs = 9; ibs = 10; ilg = 11; ilb = 12; iW1 = 13; ias1 = 14;
        iad1 = 15; ib1 = 16; iW2 = 17; ias2 = 18; iad2 = 19; ib2 = 20;
        iWo1 = 21; ibo1 = 22; iWo2 = 23; ibo2 = 24; im = 25; iei = 26;
    }
    const float* t   = (const float*)d_in[it];
    const float* v   = (const float*)d_in[iv];
    const int*   mi  = (const int*)d_in[im];
    const int*   ei  = (const int*)d_in[iei];
    const float* Wt  = (const float*)d_in[iWt];
    const float* bt  = (const float*)d_in[ibt];
    const float* Wv  = (const float*)d_in[iWv];
    const float* bv  = (const float*)d_in[ibv];
    const float* emb = (const float*)d_in[iemb];
    const float* Wn  = (const float*)d_in[iWn];
    const float* bn  = (const float*)d_in[ibn];
    const float* Ws  = (const float*)d_in[iWs];
    const float* bs  = (const float*)d_in[ibs];
    const float* lg  = (const float*)d_in[ilg];
    const float* lb  = (const float*)d_in[ilb];
    const float* W1  = (const float*)d_in[iW1];
    const float* as1 = (const float*)d_in[ias1];
    const float* ad1 = (const float*)d_in[iad1];
    const float* b1  = (const float*)d_in[ib1];
    const float* W2  = (const float*)d_in[iW2];
    const float* as2 = (const float*)d_in[ias2];
    const float* ad2 = (const float*)d_in[iad2];
    const float* b2  = (const float*)d_in[ib2];
    const float* Wo1 = (const float*)d_in[iWo1];
    const float* bo1 = (const float*)d_in[ibo1];
    const float* Wo2 = (const float*)d_in[iWo2];
    const float* bo2 = (const float*)d_in[ibo2];
    const int* esrc = ei;
    const int* edst = ei + EE;

    float *p_xp1t;
    cudaGetSymbolAddress((void**)&p_xp1t, g_xp1t);

    k_prep<<<343, 256>>>(t, v, Wt, bt, Wv, bv, Ws, bs, emb, Wn, bn, mi, W2, W1, as1, ad1);
    k_build_hist<<<1096, 256>>>(lg, lb, edst);
    k_scan<<<1, 1024>>>();
    k_scatter_gemm<<<1096, 256>>>(esrc, edst, W1);
    k_agg4bf<<<2048, 256>>>(p_xp1t, b1);
    k_wmma_attn<<<NN / 64, 256>>>(as2, ad2);
    k_final<<<GG, 512>>>(b2, mi, Wo1, bo1, Wo2, bo2, (float*)d_out);
}